// round 1
// baseline (speedup 1.0000x reference)
#include <cuda_runtime.h>

// StochasticPool2d: 2x2 stride-2 gumbel-max stochastic pooling.
// x:      [B=32, C=64, H=224, W=224] fp32
// gumbel: [B,C,112,112,4] fp32
// out:    [B,C,112,112] fp32
//
// Pure streaming kernel: each input byte read once, no reuse. One thread
// processes 2 horizontally-adjacent output pixels so every global access is a
// 16B (x, gumbel) or 8B (out) fully-coalesced vector op.

static constexpr int Bc = 32;
static constexpr int Cc = 64;
static constexpr int Hc = 224;
static constexpr int Wc = 224;
static constexpr int NH = 112;
static constexpr int NW = 112;
static constexpr long long N_OUT   = (long long)Bc * Cc * NH * NW;   // 25,690,112
static constexpr long long N_PAIRS = N_OUT / 2;                      // 12,845,056

__device__ __forceinline__ float pick4(float v0, float v1, float v2, float v3,
                                       float g0, float g1, float g2, float g3)
{
    // score_k = (v_k > 0 ? log(v_k) : log(1)=0) + gumbel_k ; first-max argmax
    float s0 = (v0 > 0.0f ? __logf(v0) : 0.0f) + g0;
    float s1 = (v1 > 0.0f ? __logf(v1) : 0.0f) + g1;
    float s2 = (v2 > 0.0f ? __logf(v2) : 0.0f) + g2;
    float s3 = (v3 > 0.0f ? __logf(v3) : 0.0f) + g3;

    float best_s = s0;
    float best_v = v0;
    if (s1 > best_s) { best_s = s1; best_v = v1; }
    if (s2 > best_s) { best_s = s2; best_v = v2; }
    if (s3 > best_s) { best_s = s3; best_v = v3; }
    return best_v;
}

__global__ void __launch_bounds__(256)
stochastic_pool2d_kernel(const float* __restrict__ x,
                         const float* __restrict__ gum,
                         float* __restrict__ out)
{
    long long t = (long long)blockIdx.x * blockDim.x + threadIdx.x;
    if (t >= N_PAIRS) return;

    // Decompose: t -> (bc, i, jpair). jpair covers output cols [2*jpair, 2*jpair+1].
    int jp   = (int)(t % (NW / 2));
    long long r = t / (NW / 2);
    int i    = (int)(r % NH);
    long long bc = r / NH;   // fused B*C index

    // x: two rows of the 2x2 windows; 4 consecutive columns starting at 4*jp.
    const float* xrow = x + bc * (long long)(Hc * Wc) + (long long)(2 * i) * Wc + 4 * jp;
    float4 x0 = *reinterpret_cast<const float4*>(xrow);        // row 2i
    float4 x1 = *reinterpret_cast<const float4*>(xrow + Wc);   // row 2i+1

    // gumbel: [.., i, j, 4] — 2 pixels = 8 contiguous floats, 32B aligned.
    const float* gp = gum + (bc * (long long)(NH * NW) + (long long)i * NW + 2 * jp) * 4;
    float4 g0 = *reinterpret_cast<const float4*>(gp);
    float4 g1 = *reinterpret_cast<const float4*>(gp + 4);

    // Window flatten order k = di*2 + dj (row-major within 2x2).
    float2 o;
    o.x = pick4(x0.x, x0.y, x1.x, x1.y, g0.x, g0.y, g0.z, g0.w); // pixel 2*jp
    o.y = pick4(x0.z, x0.w, x1.z, x1.w, g1.x, g1.y, g1.z, g1.w); // pixel 2*jp+1

    float* op = out + bc * (long long)(NH * NW) + (long long)i * NW + 2 * jp;
    *reinterpret_cast<float2*>(op) = o;
}

extern "C" void kernel_launch(void* const* d_in, const int* in_sizes, int n_in,
                              void* d_out, int out_size)
{
    const float* x   = (const float*)d_in[0];
    const float* gum = (const float*)d_in[1];
    float* out = (float*)d_out;

    const int threads = 256;
    const int blocks  = (int)((N_PAIRS + threads - 1) / threads);  // 50,176
    stochastic_pool2d_kernel<<<blocks, threads>>>(x, gum, out);
}